// round 4
// baseline (speedup 1.0000x reference)
#include <cuda_runtime.h>

#define NN 100000
#define NE 1600000
#define SCAN_B 1024
#define NBLK ((NN + SCAN_B - 1) / SCAN_B)   // 98

// ---------------- scratch (static device globals; no runtime allocation) ----
__device__ float g_H1[NN * 128];    // x@W1 (unscaled)   [N,128]
__device__ float g_h [NN * 128];    // relu(layer1)      [N,128]
__device__ float g_H2[NN * 64];     // h@W2 (unscaled)   [N,64]
__device__ int   g_count[NN];
__device__ float g_dinv[NN];
__device__ int   g_rowptr[NN + 1];
__device__ int   g_cursor[NN];
__device__ int   g_colidx[NE];
__device__ int   g_partial[128];
__device__ int   g_is64;            // 1 if edge_index is int64, 0 if int32

// ---------------- f32x2 helpers --------------------------------------------
__device__ __forceinline__ unsigned long long pack2(float a, float b) {
    unsigned long long r;
    asm("mov.b64 %0, {%1, %2};" : "=l"(r) : "f"(a), "f"(b));
    return r;
}
__device__ __forceinline__ void fma2(unsigned long long& d,
                                     unsigned long long a,
                                     unsigned long long b) {
    asm("fma.rn.f32x2 %0, %1, %2, %0;" : "+l"(d) : "l"(a), "l"(b));
}
__device__ __forceinline__ float2 unpack2(unsigned long long v) {
    float2 f;
    asm("mov.b64 {%0, %1}, %2;" : "=f"(f.x), "=f"(f.y) : "l"(v));
    return f;
}

// ---------------- edge dtype detection --------------------------------------
// int64 node ids < 2^31  =>  every odd int32 word is a zero high-word.
// int32                  =>  odd words are real src ids (~all nonzero).
__global__ void k_detect(const int* __restrict__ ei32) {
    __shared__ int s_or;
    if (threadIdx.x == 0) s_or = 0;
    __syncthreads();
    int v = ei32[2 * threadIdx.x + 1];
    if (v != 0) atomicOr(&s_or, 1);
    __syncthreads();
    if (threadIdx.x == 0) g_is64 = (s_or == 0) ? 1 : 0;
}

// ---------------- CSR build -------------------------------------------------
__global__ void k_zero() {
    int i = blockIdx.x * blockDim.x + threadIdx.x;
    if (i < NN) g_count[i] = 0;
}

// 4 edges per thread, vectorized index loads
__global__ void k_hist(const void* __restrict__ ei) {
    int q = blockIdx.x * blockDim.x + threadIdx.x;
    if (q >= NE / 4) return;
    int d0, d1, d2, d3;
    if (g_is64) {
        const long long* p = (const long long*)ei + NE + 4 * q;
        d0 = (int)p[0]; d1 = (int)p[1]; d2 = (int)p[2]; d3 = (int)p[3];
    } else {
        int4 v = ((const int4*)((const int*)ei + NE))[q];
        d0 = v.x; d1 = v.y; d2 = v.z; d3 = v.w;
    }
    if ((unsigned)d0 < (unsigned)NN) atomicAdd(&g_count[d0], 1);
    if ((unsigned)d1 < (unsigned)NN) atomicAdd(&g_count[d1], 1);
    if ((unsigned)d2 < (unsigned)NN) atomicAdd(&g_count[d2], 1);
    if ((unsigned)d3 < (unsigned)NN) atomicAdd(&g_count[d3], 1);
}

__global__ void k_scan1() {
    __shared__ int s[SCAN_B];
    int t = threadIdx.x;
    int i = blockIdx.x * SCAN_B + t;
    s[t] = (i < NN) ? g_count[i] : 0;
    __syncthreads();
    for (int off = SCAN_B / 2; off; off >>= 1) {
        if (t < off) s[t] += s[t + off];
        __syncthreads();
    }
    if (t == 0) g_partial[blockIdx.x] = s[0];
}

__global__ void k_scan2() {
    __shared__ int s[128];
    int t = threadIdx.x;
    s[t] = (t < NBLK) ? g_partial[t] : 0;
    __syncthreads();
    if (t == 0) {
        int run = 0;
        for (int b = 0; b < NBLK; b++) { int v = s[b]; s[b] = run; run += v; }
    }
    __syncthreads();
    if (t < NBLK) g_partial[t] = s[t];
}

__global__ void k_scan3() {
    __shared__ int s[SCAN_B];
    int t = threadIdx.x;
    int i = blockIdx.x * SCAN_B + t;
    int v = (i < NN) ? g_count[i] : 0;
    s[t] = v;
    __syncthreads();
    for (int off = 1; off < SCAN_B; off <<= 1) {
        int x = (t >= off) ? s[t - off] : 0;
        __syncthreads();
        s[t] += x;
        __syncthreads();
    }
    int excl = s[t] - v + g_partial[blockIdx.x];
    if (i < NN) {
        g_rowptr[i] = excl;
        g_cursor[i] = excl;
        g_dinv[i]   = rsqrtf((float)(v + 1));
    }
    if (i == NN - 1) g_rowptr[NN] = NE;
}

__global__ void k_scatter(const void* __restrict__ ei) {
    int q = blockIdx.x * blockDim.x + threadIdx.x;
    if (q >= NE / 4) return;
    int s0, s1, s2, s3, d0, d1, d2, d3;
    if (g_is64) {
        const long long* ps = (const long long*)ei + 4 * q;
        const long long* pd = (const long long*)ei + NE + 4 * q;
        s0 = (int)ps[0]; s1 = (int)ps[1]; s2 = (int)ps[2]; s3 = (int)ps[3];
        d0 = (int)pd[0]; d1 = (int)pd[1]; d2 = (int)pd[2]; d3 = (int)pd[3];
    } else {
        int4 vs = ((const int4*)ei)[q];
        int4 vd = ((const int4*)((const int*)ei + NE))[q];
        s0 = vs.x; s1 = vs.y; s2 = vs.z; s3 = vs.w;
        d0 = vd.x; d1 = vd.y; d2 = vd.z; d3 = vd.w;
    }
#define SCAT(ss, dd) \
    if ((unsigned)(dd) < (unsigned)NN && (unsigned)(ss) < (unsigned)NN) { \
        int pos = atomicAdd(&g_cursor[dd], 1); \
        if ((unsigned)pos < (unsigned)NE) g_colidx[pos] = (ss); }
    SCAT(s0, d0) SCAT(s1, d1) SCAT(s2, d2) SCAT(s3, d3)
#undef SCAT
}

// ---------------- GEMM:  out[m, BN] = A[m, :128] @ W[:128, :BN]  (unscaled) -
// 64 rows/block, 256 threads = (ty 0..7 -> 8 rows) x (tx 0..31 -> BN cols)
// A tile in 32KB smem; W streamed from global (<=64KB, L1-resident).
template <int BN>
__global__ void k_gemm(const float* __restrict__ Ain,
                       const float* __restrict__ W) {
    __shared__ float As[64 * 128];   // 32 KB
    const int tid = threadIdx.x;
    const int tx = tid & 31, ty = tid >> 5;
    const int rowBase = blockIdx.x * 64;

    const float* Ap;
    if constexpr (BN == 128) Ap = Ain; else Ap = (const float*)g_h;

    {   // stage A tile (64x128), float4, guarded
        const float4* A4 = (const float4*)Ap;
        float4* As4 = (float4*)As;
#pragma unroll
        for (int i = 0; i < 8; i++) {
            int f = tid + i * 256;
            int r = f >> 5, c4 = f & 31;
            int gr = rowBase + r;
            As4[f] = (gr < NN) ? A4[gr * 32 + c4] : make_float4(0.f, 0.f, 0.f, 0.f);
        }
    }
    __syncthreads();

    constexpr int NP = BN / 64;
    unsigned long long acc[8][NP];
#pragma unroll
    for (int r = 0; r < 8; r++)
#pragma unroll
        for (int p = 0; p < NP; p++) acc[r][p] = 0ull;

    const float4* As4 = (const float4*)As;

#pragma unroll 4
    for (int k = 0; k < 128; k += 4) {
        unsigned long long breg[4][NP];
#pragma unroll
        for (int kk = 0; kk < 4; kk++) {
            if constexpr (NP == 2) {
                ulonglong2 bb = __ldg(&((const ulonglong2*)W)[(k + kk) * 32 + tx]);
                breg[kk][0] = bb.x; breg[kk][1] = bb.y;
            } else {
                breg[kk][0] = __ldg(&((const unsigned long long*)W)[(k + kk) * 32 + tx]);
            }
        }
#pragma unroll
        for (int r = 0; r < 8; r++) {
            float4 a4 = As4[(ty * 8 + r) * 32 + (k >> 2)];
            unsigned long long aa;
            aa = pack2(a4.x, a4.x);
#pragma unroll
            for (int p = 0; p < NP; p++) fma2(acc[r][p], aa, breg[0][p]);
            aa = pack2(a4.y, a4.y);
#pragma unroll
            for (int p = 0; p < NP; p++) fma2(acc[r][p], aa, breg[1][p]);
            aa = pack2(a4.z, a4.z);
#pragma unroll
            for (int p = 0; p < NP; p++) fma2(acc[r][p], aa, breg[2][p]);
            aa = pack2(a4.w, a4.w);
#pragma unroll
            for (int p = 0; p < NP; p++) fma2(acc[r][p], aa, breg[3][p]);
        }
    }

#pragma unroll
    for (int r = 0; r < 8; r++) {
        int gr = rowBase + ty * 8 + r;
        if (gr < NN) {
            if constexpr (BN == 128) {
                float2 f0 = unpack2(acc[r][0]), f1 = unpack2(acc[r][1]);
                ((float4*)g_H1)[gr * 32 + tx] = make_float4(f0.x, f0.y, f1.x, f1.y);
            } else {
                float2 f0 = unpack2(acc[r][0]);
                ((float2*)g_H2)[gr * 32 + tx] = make_float2(f0.x, f0.y);
            }
        }
    }
}

// ---------------- Aggregation (pull, CSR), one warp per node ----------------
// out[d] = dinv[d] * ( sum_s dinv[s]*H[s]  +  dinv[d]*H[d] ) + b
__global__ void k_agg1(const float* __restrict__ b1) {
    int gw = (blockIdx.x * blockDim.x + threadIdx.x) >> 5;
    int lane = threadIdx.x & 31;
    const float4* __restrict__ H = (const float4*)g_H1;
    int beg = g_rowptr[gw], end = g_rowptr[gw + 1];
    float di = g_dinv[gw];
    float4 self = H[gw * 32 + lane];
    unsigned long long a01 = pack2(self.x * di, self.y * di);
    unsigned long long a23 = pack2(self.z * di, self.w * di);
    int j = beg;
    while (j < end) {
        int cnt = end - j; if (cnt > 32) cnt = 32;
        int   idx = (lane < cnt) ? g_colidx[j + lane] : 0;
        float ds  = g_dinv[idx];
        int t = 0;
        for (; t + 4 <= cnt; t += 4) {
#pragma unroll
            for (int u = 0; u < 4; u++) {
                int   s = __shfl_sync(0xffffffffu, idx, t + u);
                float w = __shfl_sync(0xffffffffu, ds,  t + u);
                float4 v = H[s * 32 + lane];
                unsigned long long ww = pack2(w, w);
                fma2(a01, ww, pack2(v.x, v.y));
                fma2(a23, ww, pack2(v.z, v.w));
            }
        }
        for (; t < cnt; t++) {
            int   s = __shfl_sync(0xffffffffu, idx, t);
            float w = __shfl_sync(0xffffffffu, ds,  t);
            float4 v = H[s * 32 + lane];
            unsigned long long ww = pack2(w, w);
            fma2(a01, ww, pack2(v.x, v.y));
            fma2(a23, ww, pack2(v.z, v.w));
        }
        j += cnt;
    }
    float2 r01 = unpack2(a01), r23 = unpack2(a23);
    float4 bb = ((const float4*)b1)[lane];
    float4 o;
    o.x = fmaxf(fmaf(r01.x, di, bb.x), 0.f);
    o.y = fmaxf(fmaf(r01.y, di, bb.y), 0.f);
    o.z = fmaxf(fmaf(r23.x, di, bb.z), 0.f);
    o.w = fmaxf(fmaf(r23.y, di, bb.w), 0.f);
    ((float4*)g_h)[gw * 32 + lane] = o;
}

__global__ void k_agg2(const float* __restrict__ b2, float* __restrict__ outp) {
    int gw = (blockIdx.x * blockDim.x + threadIdx.x) >> 5;
    int lane = threadIdx.x & 31;
    const float2* __restrict__ H = (const float2*)g_H2;
    int beg = g_rowptr[gw], end = g_rowptr[gw + 1];
    float di = g_dinv[gw];
    float2 self = H[gw * 32 + lane];
    unsigned long long a01 = pack2(self.x * di, self.y * di);
    int j = beg;
    while (j < end) {
        int cnt = end - j; if (cnt > 32) cnt = 32;
        int   idx = (lane < cnt) ? g_colidx[j + lane] : 0;
        float ds  = g_dinv[idx];
        int t = 0;
        for (; t + 4 <= cnt; t += 4) {
#pragma unroll
            for (int u = 0; u < 4; u++) {
                int   s = __shfl_sync(0xffffffffu, idx, t + u);
                float w = __shfl_sync(0xffffffffu, ds,  t + u);
                float2 v = H[s * 32 + lane];
                fma2(a01, pack2(w, w), pack2(v.x, v.y));
            }
        }
        for (; t < cnt; t++) {
            int   s = __shfl_sync(0xffffffffu, idx, t);
            float w = __shfl_sync(0xffffffffu, ds,  t);
            float2 v = H[s * 32 + lane];
            fma2(a01, pack2(w, w), pack2(v.x, v.y));
        }
        j += cnt;
    }
    float2 r01 = unpack2(a01);
    float2 bb = ((const float2*)b2)[lane];
    ((float2*)outp)[gw * 32 + lane] =
        make_float2(fmaf(r01.x, di, bb.x), fmaf(r01.y, di, bb.y));
}

// ---------------- launch ----------------------------------------------------
extern "C" void kernel_launch(void* const* d_in, const int* in_sizes, int n_in,
                              void* d_out, int out_size) {
    // Identify inputs by element count (all six are distinct).
    const float* x  = 0;
    const float* W1 = 0;
    const float* b1 = 0;
    const float* W2 = 0;
    const float* b2 = 0;
    const void*  ei = 0;
    for (int i = 0; i < n_in; i++) {
        switch (in_sizes[i]) {
            case NN * 128:  x  = (const float*)d_in[i]; break;
            case 128 * 128: W1 = (const float*)d_in[i]; break;
            case 128:       b1 = (const float*)d_in[i]; break;
            case 128 * 64:  W2 = (const float*)d_in[i]; break;
            case 64:        b2 = (const float*)d_in[i]; break;
            case 2 * NE:    ei = (const void*)d_in[i];  break;
            default: break;
        }
    }

    const int EB4 = (NE / 4 + 255) / 256;     // 1563
    const int GB  = (NN + 63) / 64;           // 1563
    const int AB  = (NN / 8);                 // 12500 blocks * 8 warps

    // Fork CSR build onto a side stream so it overlaps gemm1 (which no longer
    // depends on dinv). Stream/events are created per call and intentionally
    // not destroyed: destroying a stream that participated in an active
    // capture invalidates the capture, and kernel_launch runs only a handful
    // of times (replays execute the captured graph, not this function).
    cudaStream_t sB;
    cudaStreamCreateWithFlags(&sB, cudaStreamNonBlocking);
    cudaEvent_t eFork, eJoin;
    cudaEventCreateWithFlags(&eFork, cudaEventDisableTiming);
    cudaEventCreateWithFlags(&eJoin, cudaEventDisableTiming);

    cudaEventRecord(eFork, 0);
    cudaStreamWaitEvent(sB, eFork, 0);

    // Chain B: CSR build (independent of gemm1)
    k_detect<<<1, 256, 0, sB>>>((const int*)ei);
    k_zero<<<(NN + 255) / 256, 256, 0, sB>>>();
    k_hist<<<EB4, 256, 0, sB>>>(ei);
    k_scan1<<<NBLK, SCAN_B, 0, sB>>>();
    k_scan2<<<1, 128, 0, sB>>>();
    k_scan3<<<NBLK, SCAN_B, 0, sB>>>();
    k_scatter<<<EB4, 256, 0, sB>>>(ei);
    cudaEventRecord(eJoin, sB);

    // Chain A: dense GEMM1, overlapped with chain B
    k_gemm<128><<<GB, 256>>>(x, W1);

    // Join, then the dependent tail
    cudaStreamWaitEvent(0, eJoin, 0);
    k_agg1<<<AB, 256>>>(b1);
    k_gemm<64><<<GB, 256>>>(0, W2);
    k_agg2<<<AB, 256>>>(b2, (float*)d_out);
}

// round 5
// speedup vs baseline: 1.1281x; 1.1281x over previous
#include <cuda_runtime.h>
#include <cuda_fp16.h>

#define NN 100000
#define NE 1600000
#define SCAN_B 1024
#define NBLK ((NN + SCAN_B - 1) / SCAN_B)   // 98

// ---------------- scratch (static device globals; no runtime allocation) ----
__device__ unsigned g_Hs1h[NN * 64]; // (x@W1)*dinv as half2 pairs [N,128ch]
__device__ float g_h [NN * 128];     // relu(layer1)      [N,128]
__device__ float g_Hs2[NN * 64];     // (h@W2)*dinv       [N,64]
__device__ int   g_count[NN];
__device__ float g_dinv[NN];
__device__ int   g_rowptr[NN + 1];
__device__ int   g_cursor[NN];
__device__ int   g_colidx[NE];
__device__ int   g_partial[128];
__device__ int   g_is64;            // 1 if edge_index is int64, 0 if int32

// ---------------- f32x2 helpers --------------------------------------------
__device__ __forceinline__ unsigned long long pack2(float a, float b) {
    unsigned long long r;
    asm("mov.b64 %0, {%1, %2};" : "=l"(r) : "f"(a), "f"(b));
    return r;
}
__device__ __forceinline__ void fma2(unsigned long long& d,
                                     unsigned long long a,
                                     unsigned long long b) {
    asm("fma.rn.f32x2 %0, %1, %2, %0;" : "+l"(d) : "l"(a), "l"(b));
}
__device__ __forceinline__ float2 unpack2(unsigned long long v) {
    float2 f;
    asm("mov.b64 {%0, %1}, %2;" : "=f"(f.x), "=f"(f.y) : "l"(v));
    return f;
}

// ---------------- edge dtype detection --------------------------------------
// int64 node ids < 2^31  =>  every odd int32 word is a zero high-word.
// int32                  =>  odd words are real src ids (~all nonzero).
__global__ void k_detect(const int* __restrict__ ei32) {
    __shared__ int s_or;
    if (threadIdx.x == 0) s_or = 0;
    __syncthreads();
    int v = ei32[2 * threadIdx.x + 1];
    if (v != 0) atomicOr(&s_or, 1);
    __syncthreads();
    if (threadIdx.x == 0) g_is64 = (s_or == 0) ? 1 : 0;
}

// ---------------- CSR build -------------------------------------------------
__global__ void k_zero() {
    int i = blockIdx.x * blockDim.x + threadIdx.x;
    if (i < NN) g_count[i] = 0;
}

// 4 edges per thread, vectorized index loads
__global__ void k_hist(const void* __restrict__ ei) {
    int q = blockIdx.x * blockDim.x + threadIdx.x;
    if (q >= NE / 4) return;
    int d0, d1, d2, d3;
    if (g_is64) {
        const long long* p = (const long long*)ei + NE + 4 * q;
        d0 = (int)p[0]; d1 = (int)p[1]; d2 = (int)p[2]; d3 = (int)p[3];
    } else {
        int4 v = ((const int4*)((const int*)ei + NE))[q];
        d0 = v.x; d1 = v.y; d2 = v.z; d3 = v.w;
    }
    if ((unsigned)d0 < (unsigned)NN) atomicAdd(&g_count[d0], 1);
    if ((unsigned)d1 < (unsigned)NN) atomicAdd(&g_count[d1], 1);
    if ((unsigned)d2 < (unsigned)NN) atomicAdd(&g_count[d2], 1);
    if ((unsigned)d3 < (unsigned)NN) atomicAdd(&g_count[d3], 1);
}

__global__ void k_scan1() {
    __shared__ int s[SCAN_B];
    int t = threadIdx.x;
    int i = blockIdx.x * SCAN_B + t;
    s[t] = (i < NN) ? g_count[i] : 0;
    __syncthreads();
    for (int off = SCAN_B / 2; off; off >>= 1) {
        if (t < off) s[t] += s[t + off];
        __syncthreads();
    }
    if (t == 0) g_partial[blockIdx.x] = s[0];
}

__global__ void k_scan2() {
    __shared__ int s[128];
    int t = threadIdx.x;
    s[t] = (t < NBLK) ? g_partial[t] : 0;
    __syncthreads();
    if (t == 0) {
        int run = 0;
        for (int b = 0; b < NBLK; b++) { int v = s[b]; s[b] = run; run += v; }
    }
    __syncthreads();
    if (t < NBLK) g_partial[t] = s[t];
}

__global__ void k_scan3() {
    __shared__ int s[SCAN_B];
    int t = threadIdx.x;
    int i = blockIdx.x * SCAN_B + t;
    int v = (i < NN) ? g_count[i] : 0;
    s[t] = v;
    __syncthreads();
    for (int off = 1; off < SCAN_B; off <<= 1) {
        int x = (t >= off) ? s[t - off] : 0;
        __syncthreads();
        s[t] += x;
        __syncthreads();
    }
    int excl = s[t] - v + g_partial[blockIdx.x];
    if (i < NN) {
        g_rowptr[i] = excl;
        g_cursor[i] = excl;
        g_dinv[i]   = rsqrtf((float)(v + 1));
    }
    if (i == NN - 1) g_rowptr[NN] = NE;
}

__global__ void k_scatter(const void* __restrict__ ei) {
    int q = blockIdx.x * blockDim.x + threadIdx.x;
    if (q >= NE / 4) return;
    int s0, s1, s2, s3, d0, d1, d2, d3;
    if (g_is64) {
        const long long* ps = (const long long*)ei + 4 * q;
        const long long* pd = (const long long*)ei + NE + 4 * q;
        s0 = (int)ps[0]; s1 = (int)ps[1]; s2 = (int)ps[2]; s3 = (int)ps[3];
        d0 = (int)pd[0]; d1 = (int)pd[1]; d2 = (int)pd[2]; d3 = (int)pd[3];
    } else {
        int4 vs = ((const int4*)ei)[q];
        int4 vd = ((const int4*)((const int*)ei + NE))[q];
        s0 = vs.x; s1 = vs.y; s2 = vs.z; s3 = vs.w;
        d0 = vd.x; d1 = vd.y; d2 = vd.z; d3 = vd.w;
    }
#define SCAT(ss, dd) \
    if ((unsigned)(dd) < (unsigned)NN && (unsigned)(ss) < (unsigned)NN) { \
        int pos = atomicAdd(&g_cursor[dd], 1); \
        if ((unsigned)pos < (unsigned)NE) g_colidx[pos] = (ss); }
    SCAT(s0, d0) SCAT(s1, d1) SCAT(s2, d2) SCAT(s3, d3)
#undef SCAT
}

// ---------------- GEMM:  Hs[m, BN] = (A[m, :128] @ W[:128, :BN]) * dinv[m] --
// 64 rows/block, 256 threads = (ty 0..7 -> 8 rows) x (tx 0..31 -> BN cols)
// A tile in 32KB smem; W streamed from global (<=64KB, L1-resident).
// BN==128 -> writes g_Hs1h (fp16 pairs).  BN==64 -> writes g_Hs2 (fp32).
template <int BN>
__global__ void k_gemm(const float* __restrict__ Ain,
                       const float* __restrict__ W) {
    __shared__ float As[64 * 128];   // 32 KB
    const int tid = threadIdx.x;
    const int tx = tid & 31, ty = tid >> 5;
    const int rowBase = blockIdx.x * 64;

    const float* Ap;
    if constexpr (BN == 128) Ap = Ain; else Ap = (const float*)g_h;

    {   // stage A tile (64x128), float4, guarded
        const float4* A4 = (const float4*)Ap;
        float4* As4 = (float4*)As;
#pragma unroll
        for (int i = 0; i < 8; i++) {
            int f = tid + i * 256;
            int r = f >> 5, c4 = f & 31;
            int gr = rowBase + r;
            As4[f] = (gr < NN) ? A4[gr * 32 + c4] : make_float4(0.f, 0.f, 0.f, 0.f);
        }
    }
    __syncthreads();

    constexpr int NP = BN / 64;
    unsigned long long acc[8][NP];
#pragma unroll
    for (int r = 0; r < 8; r++)
#pragma unroll
        for (int p = 0; p < NP; p++) acc[r][p] = 0ull;

    const float4* As4 = (const float4*)As;

#pragma unroll 4
    for (int k = 0; k < 128; k += 4) {
        unsigned long long breg[4][NP];
#pragma unroll
        for (int kk = 0; kk < 4; kk++) {
            if constexpr (NP == 2) {
                ulonglong2 bb = __ldg(&((const ulonglong2*)W)[(k + kk) * 32 + tx]);
                breg[kk][0] = bb.x; breg[kk][1] = bb.y;
            } else {
                breg[kk][0] = __ldg(&((const unsigned long long*)W)[(k + kk) * 32 + tx]);
            }
        }
#pragma unroll
        for (int r = 0; r < 8; r++) {
            float4 a4 = As4[(ty * 8 + r) * 32 + (k >> 2)];
            unsigned long long aa;
            aa = pack2(a4.x, a4.x);
#pragma unroll
            for (int p = 0; p < NP; p++) fma2(acc[r][p], aa, breg[0][p]);
            aa = pack2(a4.y, a4.y);
#pragma unroll
            for (int p = 0; p < NP; p++) fma2(acc[r][p], aa, breg[1][p]);
            aa = pack2(a4.z, a4.z);
#pragma unroll
            for (int p = 0; p < NP; p++) fma2(acc[r][p], aa, breg[2][p]);
            aa = pack2(a4.w, a4.w);
#pragma unroll
            for (int p = 0; p < NP; p++) fma2(acc[r][p], aa, breg[3][p]);
        }
    }

#pragma unroll
    for (int r = 0; r < 8; r++) {
        int gr = rowBase + ty * 8 + r;
        if (gr < NN) {
            float di = g_dinv[gr];
            if constexpr (BN == 128) {
                // cols 4tx..4tx+3, scaled, packed to 2x half2
                float2 f0 = unpack2(acc[r][0]), f1 = unpack2(acc[r][1]);
                __half2 h0 = __floats2half2_rn(f0.x * di, f0.y * di);
                __half2 h1 = __floats2half2_rn(f1.x * di, f1.y * di);
                uint2 u;
                u.x = *(unsigned*)&h0;
                u.y = *(unsigned*)&h1;
                ((uint2*)g_Hs1h)[gr * 32 + tx] = u;
            } else {
                float2 f0 = unpack2(acc[r][0]);
                ((float2*)g_Hs2)[gr * 32 + tx] = make_float2(f0.x * di, f0.y * di);
            }
        }
    }
}

// ---------------- Aggregation (pull, CSR), one warp per node ----------------
// layer 1: gathers fp16 rows (256B/row), accumulates fp32.
// g_h = relu(dinv*(sum + self) + b1), where Hs rows are already dinv[s]-scaled.
__global__ void k_agg1(const float* __restrict__ b1) {
    int gw = (blockIdx.x * blockDim.x + threadIdx.x) >> 5;   // node id, exact
    int lane = threadIdx.x & 31;
    const uint2* __restrict__ H = (const uint2*)g_Hs1h;
    int beg = g_rowptr[gw], end = g_rowptr[gw + 1];
    uint2 sv = H[gw * 32 + lane];     // self term (pre-scaled by dinv[gw])
    float2 s0 = __half22float2(*(__half2*)&sv.x);
    float2 s1 = __half22float2(*(__half2*)&sv.y);
    float4 acc = make_float4(s0.x, s0.y, s1.x, s1.y);
    int j = beg;
    while (j < end) {
        int cnt = end - j; if (cnt > 32) cnt = 32;
        int idx = (lane < cnt) ? g_colidx[j + lane] : 0;
        int t = 0;
        for (; t + 4 <= cnt; t += 4) {
#pragma unroll
            for (int u = 0; u < 4; u++) {
                int s = __shfl_sync(0xffffffffu, idx, t + u);
                uint2 v = H[s * 32 + lane];
                float2 v0 = __half22float2(*(__half2*)&v.x);
                float2 v1 = __half22float2(*(__half2*)&v.y);
                acc.x += v0.x; acc.y += v0.y; acc.z += v1.x; acc.w += v1.y;
            }
        }
        for (; t < cnt; t++) {
            int s = __shfl_sync(0xffffffffu, idx, t);
            uint2 v = H[s * 32 + lane];
            float2 v0 = __half22float2(*(__half2*)&v.x);
            float2 v1 = __half22float2(*(__half2*)&v.y);
            acc.x += v0.x; acc.y += v0.y; acc.z += v1.x; acc.w += v1.y;
        }
        j += cnt;
    }
    float di = g_dinv[gw];
    float4 bb = ((const float4*)b1)[lane];
    float4 o;
    o.x = fmaxf(fmaf(acc.x, di, bb.x), 0.f);
    o.y = fmaxf(fmaf(acc.y, di, bb.y), 0.f);
    o.z = fmaxf(fmaf(acc.z, di, bb.z), 0.f);
    o.w = fmaxf(fmaf(acc.w, di, bb.w), 0.f);
    ((float4*)g_h)[gw * 32 + lane] = o;
}

// layer 2: fp32, 64 ch -> lane owns float2; out = dinv*(sum+self) + b2
__global__ void k_agg2(const float* __restrict__ b2, float* __restrict__ outp) {
    int gw = (blockIdx.x * blockDim.x + threadIdx.x) >> 5;
    int lane = threadIdx.x & 31;
    const float2* __restrict__ Hs = (const float2*)g_Hs2;
    int beg = g_rowptr[gw], end = g_rowptr[gw + 1];
    float2 acc = Hs[gw * 32 + lane];
    int j = beg;
    while (j < end) {
        int cnt = end - j; if (cnt > 32) cnt = 32;
        int idx = (lane < cnt) ? g_colidx[j + lane] : 0;
        int t = 0;
        for (; t + 4 <= cnt; t += 4) {
            int s0 = __shfl_sync(0xffffffffu, idx, t);
            int s1 = __shfl_sync(0xffffffffu, idx, t + 1);
            int s2 = __shfl_sync(0xffffffffu, idx, t + 2);
            int s3 = __shfl_sync(0xffffffffu, idx, t + 3);
            float2 v0 = Hs[s0 * 32 + lane];
            float2 v1 = Hs[s1 * 32 + lane];
            float2 v2 = Hs[s2 * 32 + lane];
            float2 v3 = Hs[s3 * 32 + lane];
            acc.x += (v0.x + v1.x) + (v2.x + v3.x);
            acc.y += (v0.y + v1.y) + (v2.y + v3.y);
        }
        for (; t < cnt; t++) {
            int s = __shfl_sync(0xffffffffu, idx, t);
            float2 v = Hs[s * 32 + lane];
            acc.x += v.x; acc.y += v.y;
        }
        j += cnt;
    }
    float di = g_dinv[gw];
    float2 bb = ((const float2*)b2)[lane];
    ((float2*)outp)[gw * 32 + lane] =
        make_float2(fmaf(acc.x, di, bb.x), fmaf(acc.y, di, bb.y));
}

// ---------------- launch ----------------------------------------------------
extern "C" void kernel_launch(void* const* d_in, const int* in_sizes, int n_in,
                              void* d_out, int out_size) {
    // Identify inputs by element count (all six are distinct).
    const float* x  = 0;
    const float* W1 = 0;
    const float* b1 = 0;
    const float* W2 = 0;
    const float* b2 = 0;
    const void*  ei = 0;
    for (int i = 0; i < n_in; i++) {
        switch (in_sizes[i]) {
            case NN * 128:  x  = (const float*)d_in[i]; break;
            case 128 * 128: W1 = (const float*)d_in[i]; break;
            case 128:       b1 = (const float*)d_in[i]; break;
            case 128 * 64:  W2 = (const float*)d_in[i]; break;
            case 64:        b2 = (const float*)d_in[i]; break;
            case 2 * NE:    ei = (const void*)d_in[i];  break;
            default: break;
        }
    }

    const int EB4 = (NE / 4 + 255) / 256;     // 1563
    const int GB  = (NN + 63) / 64;           // 1563
    const int AB  = (NN / 8);                 // 12500 blocks * 8 warps

    // Serial pipeline (R4 showed overlapping the CSR chain with gemm1 is
    // net-negative: both are memory-system-bound and interfere).
    k_detect<<<1, 256>>>((const int*)ei);
    k_zero<<<(NN + 255) / 256, 256>>>();
    k_hist<<<EB4, 256>>>(ei);
    k_scan1<<<NBLK, SCAN_B>>>();
    k_scan2<<<1, 128>>>();
    k_scan3<<<NBLK, SCAN_B>>>();
    k_scatter<<<EB4, 256>>>(ei);

    k_gemm<128><<<GB, 256>>>(x, W1);
    k_agg1<<<AB, 256>>>(b1);
    k_gemm<64><<<GB, 256>>>(0, W2);
    k_agg2<<<AB, 256>>>(b2, (float*)d_out);
}